// round 1
// baseline (speedup 1.0000x reference)
#include <cuda_runtime.h>

#define NN 65536
#define KK 8192
#define DD 256
#define BM 128
#define BK 128
#define AS_LD 257   // padded stride (odd) so the two ty-broadcast rows hit different banks
#define SMEM_FLOATS (BM*AS_LD + 2*16*BK)
#define SMEM_BYTES (SMEM_FLOATS * 4)

__device__ float g_z2[NN];
__device__ float g_e2[KK];
__device__ int   g_idx[NN];

// ---------------------------------------------------------------------------
// Row squared-norms. Reference computes fl(x*x) elementwise (fp32) then sums.
// We sum the fp32 squares in double and round once (correctly-rounded sum of
// the reference's summands) — errors vs any fp32 summation order are ~1e-9,
// absorbed by the final distance rounding at ulp(256)=3e-5 almost always.
// ---------------------------------------------------------------------------
__global__ void row_norm_kernel(const float* __restrict__ x, int which) {
    int row  = blockIdx.x * 8 + (threadIdx.x >> 5);
    int lane = threadIdx.x & 31;
    const float* p = x + (size_t)row * DD;
    double s = 0.0;
    #pragma unroll
    for (int i = 0; i < DD / 32; ++i) {
        float v = p[lane + i * 32];
        float q = v * v;          // fp32-rounded square, like the reference
        s += (double)q;
    }
    #pragma unroll
    for (int o = 16; o; o >>= 1) s += __shfl_xor_sync(0xffffffffu, s, o);
    if (lane == 0) {
        if (which) g_e2[row] = (float)s;
        else       g_z2[row] = (float)s;
    }
}

// ---------------------------------------------------------------------------
// Fused fp32 GEMM + argmin.
// Block: 256 threads (16x16), BM=128 rows, k-tiles of BK=128, full D=256 of
// the z tile resident in smem. Per-thread 8x8 register tile. d accumulated
// strictly sequentially (chunk-ascending, dd-ascending) in fp32 fma.
// Epilogue reproduces reference rounding: fl(fl(z2+e2) - 2*dot), argmin with
// first-index tie-break (ascending k scan, strict <; lexicographic reduce).
// ---------------------------------------------------------------------------
__global__ void __launch_bounds__(256, 1)
vq_argmin_kernel(const float* __restrict__ z, const float* __restrict__ e) {
    extern __shared__ float sm[];
    float* As = sm;                    // [BM][AS_LD], layout As[m][d]
    float* Bs = sm + BM * AS_LD;       // [2][16][BK], layout Bs[buf][dd][k]

    int tid = threadIdx.x;
    int tx = tid & 15, ty = tid >> 4;
    int mBase = blockIdx.x * BM;

    // ---- load z tile (BM x 256) into smem, As[m][d] ----
    {
        const float4* zp = (const float4*)(z + (size_t)mBase * DD);
        #pragma unroll
        for (int it = 0; it < 32; ++it) {
            int lin = tid + it * 256;      // 0 .. 8191
            int m  = lin >> 6;             // row 0..127
            int dg = lin & 63;             // float4 index in row
            float4 v = zp[(size_t)m * 64 + dg];
            float* dst = As + (size_t)m * AS_LD + dg * 4;
            dst[0] = v.x; dst[1] = v.y; dst[2] = v.z; dst[3] = v.w;
        }
    }

    float z2r[8];
    #pragma unroll
    for (int i = 0; i < 8; ++i) z2r[i] = g_z2[mBase + i * 16 + ty];

    float minv[8];
    int   mink[8];
    #pragma unroll
    for (int i = 0; i < 8; ++i) { minv[i] = __int_as_float(0x7f800000); mink[i] = 0; }

    __syncthreads();

    const float4* ep = (const float4*)e;
    int kA = tid >> 2, dgA = tid & 3;      // this thread's two B elements/chunk
    int kB = kA + 64,  dgB = dgA;

    #pragma unroll 1
    for (int kt = 0; kt < KK; kt += BK) {
        float acc[8][8];
        #pragma unroll
        for (int i = 0; i < 8; ++i)
            #pragma unroll
            for (int j = 0; j < 8; ++j) acc[i][j] = 0.0f;

        size_t baseA = (size_t)(kt + kA) * 64 + dgA;
        size_t baseB = (size_t)(kt + kB) * 64 + dgB;

        // prefetch + store chunk 0 into buffer 0 (transposed: Bs[dd][k])
        float4 nA = ep[baseA];
        float4 nB = ep[baseB];
        {
            float* Bn = Bs;
            Bn[(dgA * 4 + 0) * BK + kA] = nA.x;
            Bn[(dgA * 4 + 1) * BK + kA] = nA.y;
            Bn[(dgA * 4 + 2) * BK + kA] = nA.z;
            Bn[(dgA * 4 + 3) * BK + kA] = nA.w;
            Bn[(dgB * 4 + 0) * BK + kB] = nB.x;
            Bn[(dgB * 4 + 1) * BK + kB] = nB.y;
            Bn[(dgB * 4 + 2) * BK + kB] = nB.z;
            Bn[(dgB * 4 + 3) * BK + kB] = nB.w;
        }
        __syncthreads();

        #pragma unroll 1
        for (int c = 0; c < 16; ++c) {
            float* Bc = Bs + (c & 1) * (16 * BK);
            // prefetch next chunk from global while computing current
            if (c + 1 < 16) {
                nA = ep[baseA + (size_t)(c + 1) * 4];
                nB = ep[baseB + (size_t)(c + 1) * 4];
            }
            const float* Arow = As + (size_t)ty * AS_LD + c * 16;
            #pragma unroll
            for (int dd = 0; dd < 16; ++dd) {
                float a[8], b[8];
                #pragma unroll
                for (int i = 0; i < 8; ++i) a[i] = Arow[(size_t)i * 16 * AS_LD + dd];
                #pragma unroll
                for (int j = 0; j < 8; ++j) b[j] = Bc[dd * BK + j * 16 + tx];
                #pragma unroll
                for (int i = 0; i < 8; ++i)
                    #pragma unroll
                    for (int j = 0; j < 8; ++j)
                        acc[i][j] = fmaf(a[i], b[j], acc[i][j]);
            }
            if (c + 1 < 16) {
                float* Bn = Bs + ((c + 1) & 1) * (16 * BK);
                Bn[(dgA * 4 + 0) * BK + kA] = nA.x;
                Bn[(dgA * 4 + 1) * BK + kA] = nA.y;
                Bn[(dgA * 4 + 2) * BK + kA] = nA.z;
                Bn[(dgA * 4 + 3) * BK + kA] = nA.w;
                Bn[(dgB * 4 + 0) * BK + kB] = nB.x;
                Bn[(dgB * 4 + 1) * BK + kB] = nB.y;
                Bn[(dgB * 4 + 2) * BK + kB] = nB.z;
                Bn[(dgB * 4 + 3) * BK + kB] = nB.w;
            }
            __syncthreads();
        }

        // epilogue: exact reference rounding + running argmin (k ascending)
        #pragma unroll
        for (int j = 0; j < 8; ++j) {
            int k = kt + j * 16 + tx;
            float e2k = g_e2[k];
            #pragma unroll
            for (int i = 0; i < 8; ++i) {
                float t1 = z2r[i] + e2k;           // fl(z2 + e2)
                float d  = t1 - 2.0f * acc[i][j];  // fl(t1 - 2*dot)  (2*dot exact)
                if (d < minv[i]) { minv[i] = d; mink[i] = k; }
            }
        }
    }

    // cross-thread (tx) reduction: lexicographic (value, index) min.
    // xor offsets 1..8 stay inside the 16-lane ty-group of each warp.
    #pragma unroll
    for (int i = 0; i < 8; ++i) {
        float v = minv[i];
        int   k = mink[i];
        #pragma unroll
        for (int o = 1; o < 16; o <<= 1) {
            float ov = __shfl_xor_sync(0xffffffffu, v, o);
            int   ok = __shfl_xor_sync(0xffffffffu, k, o);
            if (ov < v || (ov == v && ok < k)) { v = ov; k = ok; }
        }
        if (tx == 0) g_idx[mBase + i * 16 + ty] = k;
    }
}

// ---------------------------------------------------------------------------
// Gather + writeout: quantized, straight_through (== quantized forward), idx.
// Layout inferred from out_size on the host; negative offset disables segment.
// ---------------------------------------------------------------------------
__global__ void writeout_kernel(const float* __restrict__ e, float* __restrict__ out,
                                long long q_off, long long st_off, long long idx_off) {
    int row  = blockIdx.x * 8 + (threadIdx.x >> 5);
    int lane = threadIdx.x & 31;
    int idx  = g_idx[row];
    const float4* src = (const float4*)(e + (size_t)idx * DD);
    #pragma unroll
    for (int i = 0; i < 2; ++i) {
        float4 v = src[lane + i * 32];
        if (q_off >= 0) {
            float4* q = (float4*)(out + q_off) + (size_t)row * (DD / 4);
            q[lane + i * 32] = v;
        }
        if (st_off >= 0) {
            float4* st = (float4*)(out + st_off) + (size_t)row * (DD / 4);
            st[lane + i * 32] = v;
        }
    }
    if (idx_off >= 0 && lane == 0) out[idx_off + row] = (float)idx;
}

extern "C" void kernel_launch(void* const* d_in, const int* in_sizes, int n_in,
                              void* d_out, int out_size) {
    const float* z = (const float*)d_in[0];
    const float* e = (const float*)d_in[1];
    float* out = (float*)d_out;

    cudaFuncSetAttribute(vq_argmin_kernel,
                         cudaFuncAttributeMaxDynamicSharedMemorySize, SMEM_BYTES);

    row_norm_kernel<<<NN / 8, 256>>>(z, 0);
    row_norm_kernel<<<KK / 8, 256>>>(e, 1);
    vq_argmin_kernel<<<NN / BM, 256, SMEM_BYTES>>>(z, e);

    long long sz = out_size, pos = 0;
    long long q_off = -1, st_off = -1, idx_off = -1;
    if (sz - pos >= (long long)NN * DD) { q_off = pos;  pos += (long long)NN * DD; }
    if (sz - pos >= (long long)NN * DD) { st_off = pos; pos += (long long)NN * DD; }
    if (sz - pos >= NN)                 { idx_off = pos; }
    writeout_kernel<<<NN / 8, 256>>>(e, out, q_off, st_off, idx_off);
}

// round 2
// speedup vs baseline: 1.3368x; 1.3368x over previous
#include <cuda_runtime.h>

#define NN 65536
#define KK 8192
#define DD 256
#define BM 128
#define BN 256
#define AS_LD 132   // padded [d][m] stride (multiple of 4 for LDS.128 alignment)
#define SMEM_FLOATS (DD*AS_LD + 2*16*BN)
#define SMEM_BYTES (SMEM_FLOATS * 4)

__device__ float g_z2[NN];
__device__ float g_e2[KK];
__device__ int   g_idx[NN];

// ---------------------------------------------------------------------------
// packed-f32x2 helpers (FFMA2: 2 independent rn FMAs per issue — numerics
// identical to two fmaf calls, 2x fp32 pipe throughput on sm_103a)
// ---------------------------------------------------------------------------
__device__ __forceinline__ unsigned long long pk2(float lo, float hi) {
    unsigned long long r;
    asm("mov.b64 %0, {%1, %2};" : "=l"(r) : "f"(lo), "f"(hi));
    return r;
}
__device__ __forceinline__ void upk2(unsigned long long v, float& lo, float& hi) {
    asm("mov.b64 {%0, %1}, %2;" : "=f"(lo), "=f"(hi) : "l"(v));
}
__device__ __forceinline__ void ffma2(unsigned long long& d,
                                      unsigned long long a, unsigned long long b) {
    asm("fma.rn.f32x2 %0, %1, %2, %3;" : "=l"(d) : "l"(a), "l"(b), "l"(d));
}

// ---------------------------------------------------------------------------
// Row squared-norms: fp32 elementwise squares (like reference), summed in
// double, rounded once. Unchanged from round 1.
// ---------------------------------------------------------------------------
__global__ void row_norm_kernel(const float* __restrict__ x, int which) {
    int row  = blockIdx.x * 8 + (threadIdx.x >> 5);
    int lane = threadIdx.x & 31;
    const float* p = x + (size_t)row * DD;
    double s = 0.0;
    #pragma unroll
    for (int i = 0; i < DD / 32; ++i) {
        float v = p[lane + i * 32];
        float q = v * v;
        s += (double)q;
    }
    #pragma unroll
    for (int o = 16; o; o >>= 1) s += __shfl_xor_sync(0xffffffffu, s, o);
    if (lane == 0) {
        if (which) g_e2[row] = (float)s;
        else       g_z2[row] = (float)s;
    }
}

// ---------------------------------------------------------------------------
// Fused fp32 GEMM + argmin, packed-f32x2 inner loop.
// 256 threads (tx 0..15 over n, ty 0..15 over m). BM=128 rows, BN=256 k-tile,
// per-thread 8m x 16n register tile (acc as 8x8 f32x2 pairs over n).
// z tile transposed in smem (As[d][m]) so a-loads are LDS.128; emb chunks
// (16 d) double-buffered transposed (Bs[dd][k]) so b-loads are LDS.128 and
// each float4 is two ready-made f32x2 operands.
// Reduction order over d (chunk c asc, dd asc) identical to round 1 ->
// bit-identical distances -> identical argmin/tie behavior.
// ---------------------------------------------------------------------------
__global__ void __launch_bounds__(256, 1)
vq_argmin_kernel(const float* __restrict__ z, const float* __restrict__ e) {
    extern __shared__ float sm[];
    float* As = sm;                 // [DD][AS_LD]  transposed: As[d][m]
    float* Bs = sm + DD * AS_LD;    // [2][16][BN]  Bs[buf][dd][k]

    int tid = threadIdx.x;
    int tx = tid & 15, ty = tid >> 4;
    int mBase = blockIdx.x * BM;

    // ---- transpose-load z tile: As[d][m] ----
    {
        const float4* zp = (const float4*)(z + (size_t)mBase * DD);
        #pragma unroll
        for (int it = 0; it < 32; ++it) {
            int lin = tid + it * 256;       // 0..8191
            int m  = lin >> 6;              // 0..127
            int dg = lin & 63;              // float4 index within row
            float4 v = zp[(size_t)m * 64 + dg];
            As[(dg * 4 + 0) * AS_LD + m] = v.x;
            As[(dg * 4 + 1) * AS_LD + m] = v.y;
            As[(dg * 4 + 2) * AS_LD + m] = v.z;
            As[(dg * 4 + 3) * AS_LD + m] = v.w;
        }
    }

    float z2r[8];
    #pragma unroll
    for (int i = 0; i < 8; ++i) z2r[i] = g_z2[mBase + ty * 8 + i];

    float minv[8];
    int   mink[8];
    #pragma unroll
    for (int i = 0; i < 8; ++i) { minv[i] = __int_as_float(0x7f800000); mink[i] = 0; }

    __syncthreads();

    const float4* ep = (const float4*)e;
    int kloc = tid >> 2;     // 0..63 : k row within pass
    int dg   = tid & 3;      // which float4 of the 16-d chunk

    #pragma unroll 1
    for (int kt = 0; kt < KK; kt += BN) {
        unsigned long long acc[8][8];
        #pragma unroll
        for (int i = 0; i < 8; ++i)
            #pragma unroll
            for (int jp = 0; jp < 8; ++jp) acc[i][jp] = 0ULL;

        // this thread's global source: e[kt+kloc+64p][d = c*16 + dg*4 + q]
        const float4* eb = ep + (size_t)(kt + kloc) * 64 + dg;

        // prefetch + store chunk 0 (transposed into buffer 0)
        float4 n0 = eb[0], n1 = eb[4096], n2 = eb[8192], n3 = eb[12288];
        {
            float* Bn = Bs;
            Bn[(dg*4+0)*BN + kloc      ] = n0.x; Bn[(dg*4+1)*BN + kloc      ] = n0.y;
            Bn[(dg*4+2)*BN + kloc      ] = n0.z; Bn[(dg*4+3)*BN + kloc      ] = n0.w;
            Bn[(dg*4+0)*BN + kloc +  64] = n1.x; Bn[(dg*4+1)*BN + kloc +  64] = n1.y;
            Bn[(dg*4+2)*BN + kloc +  64] = n1.z; Bn[(dg*4+3)*BN + kloc +  64] = n1.w;
            Bn[(dg*4+0)*BN + kloc + 128] = n2.x; Bn[(dg*4+1)*BN + kloc + 128] = n2.y;
            Bn[(dg*4+2)*BN + kloc + 128] = n2.z; Bn[(dg*4+3)*BN + kloc + 128] = n2.w;
            Bn[(dg*4+0)*BN + kloc + 192] = n3.x; Bn[(dg*4+1)*BN + kloc + 192] = n3.y;
            Bn[(dg*4+2)*BN + kloc + 192] = n3.z; Bn[(dg*4+3)*BN + kloc + 192] = n3.w;
        }
        __syncthreads();

        #pragma unroll 1
        for (int c = 0; c < 16; ++c) {
            const float* Bc = Bs + (c & 1) * (16 * BN);
            if (c + 1 < 16) {
                n0 = eb[(c+1)*4];          n1 = eb[4096 + (c+1)*4];
                n2 = eb[8192 + (c+1)*4];   n3 = eb[12288 + (c+1)*4];
            }
            const float* Ac = As + (size_t)c * 16 * AS_LD + ty * 8;
            #pragma unroll
            for (int dd = 0; dd < 16; ++dd) {
                float4 a0 = *(const float4*)(Ac + dd * AS_LD);
                float4 a1 = *(const float4*)(Ac + dd * AS_LD + 4);
                unsigned long long ad[8];
                ad[0] = pk2(a0.x, a0.x); ad[1] = pk2(a0.y, a0.y);
                ad[2] = pk2(a0.z, a0.z); ad[3] = pk2(a0.w, a0.w);
                ad[4] = pk2(a1.x, a1.x); ad[5] = pk2(a1.y, a1.y);
                ad[6] = pk2(a1.z, a1.z); ad[7] = pk2(a1.w, a1.w);
                unsigned long long bp[8];
                #pragma unroll
                for (int jg = 0; jg < 4; ++jg) {
                    float4 b4 = *(const float4*)(Bc + dd * BN + jg * 64 + tx * 4);
                    bp[jg*2]   = pk2(b4.x, b4.y);
                    bp[jg*2+1] = pk2(b4.z, b4.w);
                }
                #pragma unroll
                for (int i = 0; i < 8; ++i)
                    #pragma unroll
                    for (int jp = 0; jp < 8; ++jp)
                        ffma2(acc[i][jp], ad[i], bp[jp]);
            }
            if (c + 1 < 16) {
                float* Bn = Bs + ((c + 1) & 1) * (16 * BN);
                Bn[(dg*4+0)*BN + kloc      ] = n0.x; Bn[(dg*4+1)*BN + kloc      ] = n0.y;
                Bn[(dg*4+2)*BN + kloc      ] = n0.z; Bn[(dg*4+3)*BN + kloc      ] = n0.w;
                Bn[(dg*4+0)*BN + kloc +  64] = n1.x; Bn[(dg*4+1)*BN + kloc +  64] = n1.y;
                Bn[(dg*4+2)*BN + kloc +  64] = n1.z; Bn[(dg*4+3)*BN + kloc +  64] = n1.w;
                Bn[(dg*4+0)*BN + kloc + 128] = n2.x; Bn[(dg*4+1)*BN + kloc + 128] = n2.y;
                Bn[(dg*4+2)*BN + kloc + 128] = n2.z; Bn[(dg*4+3)*BN + kloc + 128] = n2.w;
                Bn[(dg*4+0)*BN + kloc + 192] = n3.x; Bn[(dg*4+1)*BN + kloc + 192] = n3.y;
                Bn[(dg*4+2)*BN + kloc + 192] = n3.z; Bn[(dg*4+3)*BN + kloc + 192] = n3.w;
            }
            __syncthreads();
        }

        // epilogue: exact reference rounding + running argmin, k ascending
        #pragma unroll
        for (int jg = 0; jg < 4; ++jg) {
            #pragma unroll
            for (int h = 0; h < 2; ++h) {
                int k0 = kt + jg * 64 + tx * 4 + h * 2;
                float e20 = g_e2[k0];
                float e21 = g_e2[k0 + 1];
                #pragma unroll
                for (int i = 0; i < 8; ++i) {
                    float dlo, dhi;
                    upk2(acc[i][jg * 2 + h], dlo, dhi);
                    float t  = z2r[i] + e20;             // fl(z2 + e2)
                    float d0 = t - 2.0f * dlo;           // fl(t - 2*dot)
                    if (d0 < minv[i]) { minv[i] = d0; mink[i] = k0; }
                    t = z2r[i] + e21;
                    float d1 = t - 2.0f * dhi;
                    if (d1 < minv[i]) { minv[i] = d1; mink[i] = k0 + 1; }
                }
            }
        }
    }

    // cross-thread (tx, 16 lanes) lexicographic (value, index) min
    #pragma unroll
    for (int i = 0; i < 8; ++i) {
        float v = minv[i];
        int   k = mink[i];
        #pragma unroll
        for (int o = 1; o < 16; o <<= 1) {
            float ov = __shfl_xor_sync(0xffffffffu, v, o);
            int   ok = __shfl_xor_sync(0xffffffffu, k, o);
            if (ov < v || (ov == v && ok < k)) { v = ov; k = ok; }
        }
        if (tx == 0) g_idx[mBase + ty * 8 + i] = k;
    }
}

// ---------------------------------------------------------------------------
// Gather + writeout (unchanged).
// ---------------------------------------------------------------------------
__global__ void writeout_kernel(const float* __restrict__ e, float* __restrict__ out,
                                long long q_off, long long st_off, long long idx_off) {
    int row  = blockIdx.x * 8 + (threadIdx.x >> 5);
    int lane = threadIdx.x & 31;
    int idx  = g_idx[row];
    const float4* src = (const float4*)(e + (size_t)idx * DD);
    #pragma unroll
    for (int i = 0; i < 2; ++i) {
        float4 v = src[lane + i * 32];
        if (q_off >= 0) {
            float4* q = (float4*)(out + q_off) + (size_t)row * (DD / 4);
            q[lane + i * 32] = v;
        }
        if (st_off >= 0) {
            float4* st = (float4*)(out + st_off) + (size_t)row * (DD / 4);
            st[lane + i * 32] = v;
        }
    }
    if (idx_off >= 0 && lane == 0) out[idx_off + row] = (float)idx;
}

extern "C" void kernel_launch(void* const* d_in, const int* in_sizes, int n_in,
                              void* d_out, int out_size) {
    const float* z = (const float*)d_in[0];
    const float* e = (const float*)d_in[1];
    float* out = (float*)d_out;

    cudaFuncSetAttribute(vq_argmin_kernel,
                         cudaFuncAttributeMaxDynamicSharedMemorySize, SMEM_BYTES);

    row_norm_kernel<<<NN / 8, 256>>>(z, 0);
    row_norm_kernel<<<KK / 8, 256>>>(e, 1);
    vq_argmin_kernel<<<NN / BM, 256, SMEM_BYTES>>>(z, e);

    long long sz = out_size, pos = 0;
    long long q_off = -1, st_off = -1, idx_off = -1;
    if (sz - pos >= (long long)NN * DD) { q_off = pos;  pos += (long long)NN * DD; }
    if (sz - pos >= (long long)NN * DD) { st_off = pos; pos += (long long)NN * DD; }
    if (sz - pos >= NN)                 { idx_off = pos; }
    writeout_kernel<<<NN / 8, 256>>>(e, out, q_off, st_off, idx_off);
}